// round 16
// baseline (speedup 1.0000x reference)
#include <cuda_runtime.h>
#include <cuda_fp16.h>
#include <math.h>
#include <stdint.h>

#define NN 50000
#define NE 400000
#define DD 128
#define NM 20400
#define NG 30
#define LMAX 680
#define NHEADS 4
#define NL 4
#define FFD 2048
#define NCHUNK 160   // ceil(20400/128)
#define NITEMS (NE + NN)

// ---------------- scratch (device globals; no runtime allocation) ----------------
__device__ __align__(16) float  g_als3[NN * 3 * NHEADS];
__device__ __align__(16) float  g_ald3[NN * 3 * NHEADS];
__device__ __align__(16) float  g_ew[(size_t)3 * NITEMS * NHEADS];
__device__ int g_srcS[(size_t)3 * NITEMS];
__device__ int g_deg[3 * NN];
__device__ int g_off[3 * (NN + 1)];
__device__ int g_cur[3 * NN];
__device__ __align__(16) float  g_y[(size_t)NM * DD];
__device__ __align__(16) float  g_pe[NG * DD];
__device__ int g_pos[NM];
__device__ int g_cnt[NG];
// fp16 shadows / intermediates
__device__ __align__(16) __half g_x16[(size_t)NN * DD];
__device__ __align__(16) __half g_h316[(size_t)NN * 384];
__device__ __align__(16) __half g_gout316[(size_t)NN * 384];
__device__ __align__(16) __half g_y16[(size_t)NM * DD];
__device__ __align__(16) __half g_qkv16[(size_t)NM * 3 * DD];
__device__ __align__(16) __half g_attn16[(size_t)NM * DD];
__device__ __align__(16) __half g_ffn16[(size_t)NM * FFD];
__device__ __align__(16) __half g_xm16[(size_t)NM * DD];
// fp16 weights
__device__ __align__(16) __half g_gatW16[3 * DD * DD];
__device__ __align__(16) __half g_decW16[3 * DD * DD];
__device__ __align__(16) __half g_qkvW16[NL * 3 * DD * DD];
__device__ __align__(16) __half g_outW16[NL * DD * DD];
__device__ __align__(16) __half g_fw116[(size_t)NL * FFD * DD];
__device__ __align__(16) __half g_fw216[(size_t)NL * DD * FFD];
__device__ __align__(16) __half g_fusW16[DD * 256];

// ---------------- small helpers ----------------
__device__ __forceinline__ float leakyf(float x, float s) { return x >= 0.f ? x : s * x; }

__device__ __forceinline__ uint32_t f2h2(float lo, float hi) {
    uint32_t r;
    asm("cvt.rn.f16x2.f32 %0, %1, %2;" : "=r"(r) : "f"(hi), "f"(lo));
    return r;
}

__device__ __forceinline__ uint32_t h2ex2(uint32_t x) {
    uint32_t r;
    asm("ex2.approx.f16x2 %0, %1;" : "=r"(r) : "r"(x));
    return r;
}

__device__ __forceinline__ float ex2f(float x) {
    float r;
    asm("ex2.approx.f32 %0, %1;" : "=f"(r) : "f"(x));
    return r;
}

__device__ __forceinline__ uint32_t smem_u32(const void* p) {
    uint32_t a;
    asm("{ .reg .u64 t; cvta.to.shared.u64 t, %1; cvt.u32.u64 %0, t; }" : "=r"(a) : "l"(p));
    return a;
}

__device__ __forceinline__ void mma16(float* c, uint32_t a0, uint32_t a1, uint32_t a2,
                                      uint32_t a3, uint32_t b0, uint32_t b1) {
    asm volatile(
        "mma.sync.aligned.m16n8k16.row.col.f32.f16.f16.f32 "
        "{%0,%1,%2,%3}, {%4,%5,%6,%7}, {%8,%9}, {%0,%1,%2,%3};"
        : "+f"(c[0]), "+f"(c[1]), "+f"(c[2]), "+f"(c[3])
        : "r"(a0), "r"(a1), "r"(a2), "r"(a3), "r"(b0), "r"(b1));
}

// fp16 accumulator variant: C/D are 2 regs (4 halves)
__device__ __forceinline__ void mma16h(uint32_t* c, uint32_t a0, uint32_t a1, uint32_t a2,
                                       uint32_t a3, uint32_t b0, uint32_t b1) {
    asm volatile(
        "mma.sync.aligned.m16n8k16.row.col.f16.f16.f16.f16 "
        "{%0,%1}, {%2,%3,%4,%5}, {%6,%7}, {%0,%1};"
        : "+r"(c[0]), "+r"(c[1])
        : "r"(a0), "r"(a1), "r"(a2), "r"(a3), "r"(b0), "r"(b1));
}

__device__ __forceinline__ void ldsm4(uint32_t* r, uint32_t addr) {
    asm volatile("ldmatrix.sync.aligned.m8n8.x4.shared.b16 {%0,%1,%2,%3}, [%4];"
                 : "=r"(r[0]), "=r"(r[1]), "=r"(r[2]), "=r"(r[3]) : "r"(addr));
}

// ---------------- batched float -> half conversion (one launch) ----------------
struct F2HBatch {
    const float* src[8];
    __half* dst[8];
    int n4[8];
};
__global__ void f2h_multi(F2HBatch b) {
    int a = blockIdx.y;
    int n4 = b.n4[a];
    const float* s = b.src[a];
    __half* d = b.dst[a];
    for (int i = blockIdx.x * blockDim.x + threadIdx.x; i < n4; i += gridDim.x * blockDim.x) {
        float4 v = ((const float4*)s)[i];
        uint2 u;
        u.x = f2h2(v.x, v.y);
        u.y = f2h2(v.z, v.w);
        ((uint2*)d)[i] = u;
    }
}

#define SRW 20
#define TBUF (128 * SRW)

#define FRAG_SETUP                                                  \
    const int tid = threadIdx.x;                                    \
    const int wid = tid >> 5, lane = tid & 31;                      \
    const int wm = wid & 1, wn = wid >> 1;                          \
    const int lq = lane >> 2, lr = lane & 3;                        \
    const int rr = lane & 7;                                        \
    const int aRow = wm * 64 + rr + ((lane >> 3) & 1) * 8;          \
    const int aColW = ((lane >> 4) & 1) * 4;                        \
    const int bRow = wn * 32 + rr + ((lane >> 4) & 1) * 8;          \
    const int bColW = ((lane >> 3) & 1) * 4;                        \
    const int s_row = tid >> 2;                                     \
    const int s_c = tid & 3;

#define STS_CHUNK(Ad, Bd)                                           \
    {                                                               \
        _Pragma("unroll")                                           \
        for (int it = 0; it < 2; it++) {                            \
            int row = it * 64 + s_row;                              \
            *(uint4*)&(Ad)[row * SRW + s_c * 4] = pa[it];           \
            *(uint4*)&(Bd)[row * SRW + s_c * 4] = pb[it];           \
        }                                                           \
    }
#define COMPUTE_KS(AsAddr, BsAddr, KS)                                                 \
    {                                                                                  \
        uint32_t bq[2][4];                                                             \
        _Pragma("unroll")                                                              \
        for (int ntp = 0; ntp < 2; ntp++)                                              \
            ldsm4(bq[ntp], (BsAddr) + (((bRow + ntp * 16) * SRW) + (KS) * 8 + bColW) * 4); \
        _Pragma("unroll")                                                              \
        for (int mt = 0; mt < 4; mt++) {                                               \
            uint32_t aq[4];                                                            \
            ldsm4(aq, (AsAddr) + (((aRow + mt * 16) * SRW) + (KS) * 8 + aColW) * 4);   \
            _Pragma("unroll")                                                          \
            for (int nt = 0; nt < 4; nt++)                                             \
                mma16(acc[mt][nt], aq[0], aq[1], aq[2], aq[3],                         \
                      bq[nt >> 1][(nt & 1) * 2 + 0], bq[nt >> 1][(nt & 1) * 2 + 1]);   \
        }                                                                              \
    }
#define COMPUTE_KS_H(AsAddr, BsAddr, KS)                                               \
    {                                                                                  \
        uint32_t bq[2][4];                                                             \
        _Pragma("unroll")                                                              \
        for (int ntp = 0; ntp < 2; ntp++)                                              \
            ldsm4(bq[ntp], (BsAddr) + (((bRow + ntp * 16) * SRW) + (KS) * 8 + bColW) * 4); \
        _Pragma("unroll")                                                              \
        for (int mt = 0; mt < 4; mt++) {                                               \
            uint32_t aq[4];                                                            \
            ldsm4(aq, (AsAddr) + (((aRow + mt * 16) * SRW) + (KS) * 8 + aColW) * 4);   \
            _Pragma("unroll")                                                          \
            for (int nt = 0; nt < 4; nt++)                                             \
                mma16h(acch[mt][nt], aq[0], aq[1], aq[2], aq[3],                       \
                       bq[nt >> 1][(nt & 1) * 2 + 0], bq[nt >> 1][(nt & 1) * 2 + 1]);  \
        }                                                                              \
    }

#define GEMM_BODY(LDGMACRO, NCHUNKS, CKS)                                              \
    uint32_t* A0 = sm;                                                                 \
    uint32_t* B0 = sm + TBUF;                                                          \
    uint32_t* A1 = sm + 2 * TBUF;                                                      \
    uint32_t* B1 = sm + 3 * TBUF;                                                      \
    const uint32_t sb = smem_u32(sm);                                                  \
    const uint32_t aAddr0 = sb, bAddr0 = sb + TBUF * 4;                                \
    const uint32_t aAddr1 = sb + 2 * TBUF * 4, bAddr1 = sb + 3 * TBUF * 4;             \
    LDGMACRO(0);                                                                       \
    STS_CHUNK(A0, B0);                                                                 \
    if ((NCHUNKS) > 1) LDGMACRO(1);                                                    \
    __syncthreads();                                                                   \
    for (int c = 0; c < (NCHUNKS); c++) {                                              \
        uint32_t aA = (c & 1) ? aAddr1 : aAddr0;                                       \
        uint32_t bA = (c & 1) ? bAddr1 : bAddr0;                                       \
        uint32_t* Asn = (c & 1) ? A0 : A1;                                             \
        uint32_t* Bsn = (c & 1) ? B0 : B1;                                             \
        CKS(aA, bA, 0);                                                                \
        if (c + 1 < (NCHUNKS)) STS_CHUNK(Asn, Bsn);                                    \
        CKS(aA, bA, 1);                                                                \
        if (c + 2 < (NCHUNKS)) LDGMACRO(c + 2);                                        \
        __syncthreads();                                                               \
    }

// ---------------- pipelined fp16 mma GEMM (fp32 accum) ----------------
// epi: 0 = fp32 store(+bias), 3 = fp16 store -> C16, 4 = fp16 relu -> C16
__global__ __launch_bounds__(256) void gemm_mma(
    const __half* __restrict__ A, const __half* __restrict__ B,
    const float* __restrict__ bias, float* __restrict__ C, __half* __restrict__ C16,
    int M, int N, int K, int lda, int ldb, int epi)
{
    extern __shared__ uint32_t sm[];
    FRAG_SETUP
    const int row0 = blockIdx.y * 128, col0 = blockIdx.x * 128;

    float acc[4][4][4];
#pragma unroll
    for (int i = 0; i < 4; i++)
#pragma unroll
        for (int j = 0; j < 4; j++) {
            acc[i][j][0] = 0.f; acc[i][j][1] = 0.f;
            acc[i][j][2] = 0.f; acc[i][j][3] = 0.f;
        }
    const int nC = K >> 5;
    uint4 pa[2], pb[2];

#define LDG_CHUNK(cc)                                                                  \
    {                                                                                  \
        int k0 = (cc) << 5;                                                            \
        _Pragma("unroll")                                                              \
        for (int it = 0; it < 2; it++) {                                               \
            int row = it * 64 + s_row;                                                 \
            int gr = row0 + row;                                                       \
            pa[it] = make_uint4(0u, 0u, 0u, 0u);                                       \
            if (gr < M) pa[it] = *(const uint4*)(A + (size_t)gr * lda + k0 + s_c * 8); \
            pb[it] = *(const uint4*)(B + (size_t)(col0 + row) * ldb + k0 + s_c * 8);   \
        }                                                                              \
    }

    GEMM_BODY(LDG_CHUNK, nC, COMPUTE_KS)

    const int rbase = row0 + wm * 64;
    const int cbase = col0 + wn * 32;
#pragma unroll
    for (int mt = 0; mt < 4; mt++) {
        int r0 = rbase + mt * 16 + lq;
#pragma unroll
        for (int half = 0; half < 2; half++) {
            int r = r0 + half * 8;
            if (r < M) {
#pragma unroll
                for (int nt = 0; nt < 4; nt++) {
                    int c = cbase + nt * 8 + lr * 2;
                    float v0 = acc[mt][nt][half * 2 + 0];
                    float v1 = acc[mt][nt][half * 2 + 1];
                    if (bias) { v0 += bias[c]; v1 += bias[c + 1]; }
                    if (epi == 0) {
                        *(float2*)(C + (size_t)r * N + c) = make_float2(v0, v1);
                    } else if (epi == 3) {
                        *(uint32_t*)(C16 + (size_t)r * N + c) = f2h2(v0, v1);
                    } else {
                        *(uint32_t*)(C16 + (size_t)r * N + c) =
                            f2h2(fmaxf(v0, 0.f), fmaxf(v1, 0.f));
                    }
                }
            }
        }
    }
}

// ---------------- pipelined fp16 mma GEMM (fp16 accum; K <= 128 use only) ----------------
// epi: 3 = fp16 store -> C16, 4 = fp16 relu -> C16
__global__ __launch_bounds__(256) void gemm_mma_h(
    const __half* __restrict__ A, const __half* __restrict__ B,
    const float* __restrict__ bias, __half* __restrict__ C16,
    int M, int N, int K, int lda, int ldb, int epi)
{
    extern __shared__ uint32_t sm[];
    FRAG_SETUP
    const int row0 = blockIdx.y * 128, col0 = blockIdx.x * 128;

    uint32_t acch[4][4][2];
#pragma unroll
    for (int i = 0; i < 4; i++)
#pragma unroll
        for (int j = 0; j < 4; j++) { acch[i][j][0] = 0u; acch[i][j][1] = 0u; }
    const int nC = K >> 5;
    uint4 pa[2], pb[2];

#define LDG_CHUNK_H(cc)                                                                \
    {                                                                                  \
        int k0 = (cc) << 5;                                                            \
        _Pragma("unroll")                                                              \
        for (int it = 0; it < 2; it++) {                                               \
            int row = it * 64 + s_row;                                                 \
            int gr = row0 + row;                                                       \
            pa[it] = make_uint4(0u, 0u, 0u, 0u);                                       \
            if (gr < M) pa[it] = *(const uint4*)(A + (size_t)gr * lda + k0 + s_c * 8); \
            pb[it] = *(const uint4*)(B + (size_t)(col0 + row) * ldb + k0 + s_c * 8);   \
        }                                                                              \
    }

    GEMM_BODY(LDG_CHUNK_H, nC, COMPUTE_KS_H)

    const int rbase = row0 + wm * 64;
    const int cbase = col0 + wn * 32;
    const __half2 zero2 = __half2half2(__float2half(0.f));
#pragma unroll
    for (int mt = 0; mt < 4; mt++) {
        int r0 = rbase + mt * 16 + lq;
#pragma unroll
        for (int half = 0; half < 2; half++) {
            int r = r0 + half * 8;
            if (r < M) {
#pragma unroll
                for (int nt = 0; nt < 4; nt++) {
                    int c = cbase + nt * 8 + lr * 2;
                    uint32_t vr = acch[mt][nt][half];
                    __half2 v = *(__half2*)&vr;
                    if (bias) {
                        uint32_t bb = f2h2(bias[c], bias[c + 1]);
                        v = __hadd2(v, *(__half2*)&bb);
                    }
                    if (epi == 4) v = __hmax2(v, zero2);
                    *(__half2*)(C16 + (size_t)r * N + c) = v;
                }
            }
        }
    }
}

// ---------------- final fusion GEMM ----------------
__global__ __launch_bounds__(256) void gemm_fuse(
    const __half* __restrict__ A, const __half* __restrict__ B,
    const int* __restrict__ midx, const int* __restrict__ genre,
    const float* __restrict__ fb, float* __restrict__ out, int M)
{
    extern __shared__ uint32_t sm[];
    FRAG_SETUP
    const int row0 = blockIdx.y * 128;
    const int col0 = 0;
    const int ldb = 256;

    float acc[4][4][4];
#pragma unroll
    for (int i = 0; i < 4; i++)
#pragma unroll
        for (int j = 0; j < 4; j++) {
            acc[i][j][0] = 0.f; acc[i][j][1] = 0.f;
            acc[i][j][2] = 0.f; acc[i][j][3] = 0.f;
        }
    uint4 pa[2], pb[2];

#define LDG_FUSE(cc)                                                                   \
    {                                                                                  \
        int k0 = (cc) << 5;                                                            \
        _Pragma("unroll")                                                              \
        for (int it = 0; it < 2; it++) {                                               \
            int row = it * 64 + s_row;                                                 \
            int gr = row0 + row;                                                       \
            pa[it] = make_uint4(0u, 0u, 0u, 0u);                                       \
            if (gr < M) pa[it] = *(const uint4*)(A + (size_t)gr * DD + k0 + s_c * 8);  \
            pb[it] = *(const uint4*)(B + (size_t)(col0 + row) * ldb + k0 + s_c * 8);   \
        }                                                                              \
    }

    GEMM_BODY(LDG_FUSE, 4, COMPUTE_KS)

    const int rbase = row0 + wm * 64;
    const int cbase = wn * 32;
#pragma unroll
    for (int mt = 0; mt < 4; mt++) {
        int r0 = rbase + mt * 16 + lq;
#pragma unroll
        for (int half = 0; half < 2; half++) {
            int r = r0 + half * 8;
            if (r < M) {
                int gidx = genre[r];
                int orow = midx[r];
#pragma unroll
                for (int nt = 0; nt < 4; nt++) {
                    int c = cbase + nt * 8 + lr * 2;
                    float v0 = acc[mt][nt][half * 2 + 0] + g_pe[gidx * DD + c] + fb[c];
                    float v1 = acc[mt][nt][half * 2 + 1] + g_pe[gidx * DD + c + 1] + fb[c + 1];
                    *(float2*)(out + (size_t)orow * DD + c) =
                        make_float2(leakyf(v0, 0.01f), leakyf(v1, 0.01f));
                }
            }
        }
    }
}

// ---------------- GEMM (N=128) fused with residual LayerNorm ----------------
#define LNS 132
__global__ __launch_bounds__(256) void gemm_ln(
    const __half* __restrict__ A, const __half* __restrict__ B,
    const float* __restrict__ bias,
    const float* __restrict__ gam, const float* __restrict__ bet,
    float* __restrict__ y, __half* __restrict__ y16, int M, int K)
{
    extern __shared__ uint32_t sm[];
    FRAG_SETUP
    const int row0 = blockIdx.y * 128;
    const int col0 = 0;

    float acc[4][4][4];
#pragma unroll
    for (int i = 0; i < 4; i++)
#pragma unroll
        for (int j = 0; j < 4; j++) {
            acc[i][j][0] = 0.f; acc[i][j][1] = 0.f;
            acc[i][j][2] = 0.f; acc[i][j][3] = 0.f;
        }
    const int nC = K >> 5;
    uint4 pa[2], pb[2];

#define LDG_LN(cc)                                                                     \
    {                                                                                  \
        int k0 = (cc) << 5;                                                            \
        _Pragma("unroll")                                                              \
        for (int it = 0; it < 2; it++) {                                               \
            int row = it * 64 + s_row;                                                 \
            int gr = row0 + row;                                                       \
            pa[it] = make_uint4(0u, 0u, 0u, 0u);                                       \
            if (gr < M) pa[it] = *(const uint4*)(A + (size_t)gr * K + k0 + s_c * 8);   \
            pb[it] = *(const uint4*)(B + (size_t)(col0 + row) * K + k0 + s_c * 8);     \
        }                                                                              \
    }

    GEMM_BODY(LDG_LN, nC, COMPUTE_KS)

    float* stg = (float*)sm;
    const int rbl = wm * 64;
    const int cb = wn * 32;
#pragma unroll
    for (int mt = 0; mt < 4; mt++) {
#pragma unroll
        for (int half = 0; half < 2; half++) {
            int rl = rbl + mt * 16 + lq + half * 8;
#pragma unroll
            for (int nt = 0; nt < 4; nt++) {
                int c = cb + nt * 8 + lr * 2;
                float v0 = acc[mt][nt][half * 2 + 0] + bias[c];
                float v1 = acc[mt][nt][half * 2 + 1] + bias[c + 1];
                *(float2*)&stg[rl * LNS + c] = make_float2(v0, v1);
            }
        }
    }
    __syncthreads();

    float4 gg = *(const float4*)(gam + lane * 4);
    float4 bb = *(const float4*)(bet + lane * 4);
    for (int rw = 0; rw < 16; rw++) {
        int rl = wid * 16 + rw;
        int r = row0 + rl;
        if (r >= M) break;
        size_t off = (size_t)r * DD + lane * 4;
        float4 v = *(float4*)(y + off);
        float4 t4 = *(float4*)&stg[rl * LNS + lane * 4];
        v.x += t4.x; v.y += t4.y; v.z += t4.z; v.w += t4.w;
        float s = v.x + v.y + v.z + v.w;
#pragma unroll
        for (int o = 16; o > 0; o >>= 1) s += __shfl_xor_sync(0xffffffffu, s, o);
        float mean = s * (1.f / DD);
        float dx = v.x - mean, dy = v.y - mean, dz = v.z - mean, dw = v.w - mean;
        float ss = dx * dx + dy * dy + dz * dz + dw * dw;
#pragma unroll
        for (int o = 16; o > 0; o >>= 1) ss += __shfl_xor_sync(0xffffffffu, ss, o);
        float inv = rsqrtf(ss * (1.f / DD) + 1e-5f);
        v.x = dx * inv * gg.x + bb.x;
        v.y = dy * inv * gg.y + bb.y;
        v.z = dz * inv * gg.z + bb.z;
        v.w = dw * inv * gg.w + bb.w;
        *(float4*)(y + off) = v;
        *(uint2*)(y16 + off) = make_uint2(f2h2(v.x, v.y), f2h2(v.z, v.w));
    }
}

// ---------------- fused 3-hop decoder GEMM ----------------
__global__ __launch_bounds__(256) void gemm_dec(
    const __half* __restrict__ A, const __half* __restrict__ B,
    const float* __restrict__ bias, float* __restrict__ Cout, int M)
{
    extern __shared__ uint32_t sm[];
    FRAG_SETUP
    const int row0 = blockIdx.y * 128;
    const float scales[3] = {1.f, 0.90483741803596f, 0.81873075307798f};

    float acc[4][4][4], acc2[4][4][4];
#pragma unroll
    for (int i = 0; i < 4; i++)
#pragma unroll
        for (int j = 0; j < 4; j++)
#pragma unroll
            for (int k = 0; k < 4; k++) { acc[i][j][k] = 0.f; acc2[i][j][k] = 0.f; }

    uint4 pa[2], pb[2];
#define LDG_DEC(cc)                                                                    \
    {                                                                                  \
        int k0 = (cc) << 5;                                                            \
        int hop = (cc) >> 2, kb = ((cc) & 3) << 5;                                     \
        _Pragma("unroll")                                                              \
        for (int it = 0; it < 2; it++) {                                               \
            int row = it * 64 + s_row;                                                 \
            int gr = row0 + row;                                                       \
            pa[it] = make_uint4(0u, 0u, 0u, 0u);                                       \
            if (gr < M) pa[it] = *(const uint4*)(A + (size_t)gr * 384 + k0 + s_c * 8); \
            pb[it] = *(const uint4*)(B + (size_t)hop * 16384 + (size_t)row * 128 + kb + s_c * 8); \
        }                                                                              \
    }

    uint32_t* A0 = sm;
    uint32_t* B0 = sm + TBUF;
    uint32_t* A1 = sm + 2 * TBUF;
    uint32_t* B1 = sm + 3 * TBUF;
    const uint32_t sb = smem_u32(sm);
    const uint32_t aAddr0 = sb, bAddr0 = sb + TBUF * 4;
    const uint32_t aAddr1 = sb + 2 * TBUF * 4, bAddr1 = sb + 3 * TBUF * 4;
    const int cbase = wn * 32;

    LDG_DEC(0);
    STS_CHUNK(A0, B0);
    LDG_DEC(1);
    __syncthreads();

    for (int c = 0; c < 12; c++) {
        uint32_t aA = (c & 1) ? aAddr1 : aAddr0;
        uint32_t bA = (c & 1) ? bAddr1 : bAddr0;
        uint32_t* Asn = (c & 1) ? A0 : A1;
        uint32_t* Bsn = (c & 1) ? B0 : B1;
        COMPUTE_KS(aA, bA, 0);
        if (c + 1 < 12) STS_CHUNK(Asn, Bsn);
        COMPUTE_KS(aA, bA, 1);
        if (c + 2 < 12) LDG_DEC(c + 2);
        __syncthreads();
        if ((c & 3) == 3) {
            int hop = c >> 2;
            float sc = scales[hop];
#pragma unroll
            for (int nt = 0; nt < 4; nt++) {
                int col = cbase + nt * 8 + lr * 2;
                float b0 = bias[hop * 128 + col];
                float b1 = bias[hop * 128 + col + 1];
#pragma unroll
                for (int mt = 0; mt < 4; mt++) {
                    acc2[mt][nt][0] += sc * leakyf(acc[mt][nt][0] + b0, 0.01f);
                    acc2[mt][nt][1] += sc * leakyf(acc[mt][nt][1] + b1, 0.01f);
                    acc2[mt][nt][2] += sc * leakyf(acc[mt][nt][2] + b0, 0.01f);
                    acc2[mt][nt][3] += sc * leakyf(acc[mt][nt][3] + b1, 0.01f);
                    acc[mt][nt][0] = 0.f; acc[mt][nt][1] = 0.f;
                    acc[mt][nt][2] = 0.f; acc[mt][nt][3] = 0.f;
                }
            }
        }
    }

    const int rbase = row0 + wm * 64;
#pragma unroll
    for (int mt = 0; mt < 4; mt++) {
        int r0 = rbase + mt * 16 + lq;
#pragma unroll
        for (int half = 0; half < 2; half++) {
            int r = r0 + half * 8;
            if (r < M) {
#pragma unroll
                for (int nt = 0; nt < 4; nt++) {
                    int col = cbase + nt * 8 + lr * 2;
                    *(float2*)(Cout + (size_t)r * DD + col) =
                        make_float2(acc2[mt][nt][half * 2 + 0], acc2[mt][nt][half * 2 + 1]);
                }
            }
        }
    }
}

// ---------------- fp16 tensor-core flash attention (KB=64, 2 blocks/SM) ----------------
#define VSW2 36
__global__ __launch_bounds__(256, 2) void attn_tc() {
    __shared__ uint32_t QK[128 * SRW];
    __shared__ uint32_t VT[32 * VSW2];
    const int b = blockIdx.z, h = blockIdx.y, qt = blockIdx.x;
    const int cnt = g_cnt[b];
    const int tid = threadIdx.x, wid = tid >> 5, lane = tid & 31;
    const int lq = lane >> 2, lr = lane & 3;
    const float qs2 = 0.2550181731927341f;   // (1/sqrt(32)) * log2(e)
    const uint32_t ones2 = 0x3C003C00u;

#pragma unroll
    for (int it = 0; it < 4; it++) {
        int idx = it * 256 + tid;
        int row = idx >> 3;
        int q = qt * 128 + row;
        uint2 u = make_uint2(0u, 0u);
        if (q < LMAX)
            u = *(const uint2*)(g_qkv16 + (size_t)(b * LMAX + q) * 384 + h * 32 + (idx & 7) * 4);
        *(uint2*)&QK[row * SRW + (idx & 7) * 2] = u;
    }
    __syncthreads();
    uint32_t qa[2][4];
    {
        int r = wid * 16 + lq;
#pragma unroll
        for (int ks = 0; ks < 2; ks++) {
            int kb = ks * 8 + lr;
            qa[ks][0] = QK[r * SRW + kb];
            qa[ks][1] = QK[(r + 8) * SRW + kb];
            qa[ks][2] = QK[r * SRW + kb + 4];
            qa[ks][3] = QK[(r + 8) * SRW + kb + 4];
        }
    }

    float m0 = -INFINITY, m1 = -INFINITY, den0 = 0.f, den1 = 0.f;
    float of[4][4];
#pragma unroll
    for (int nt = 0; nt < 4; nt++) {
        of[nt][0] = 0.f; of[nt][1] = 0.f; of[nt][2] = 0.f; of[nt][3] = 0.f;
    }

    for (int kb0 = 0; kb0 < LMAX; kb0 += 64) {
        __syncthreads();
#pragma unroll
        for (int it = 0; it < 2; it++) {
            int idx = it * 256 + tid;
            int row = idx >> 3;
            int key = kb0 + row;
            uint2 u = make_uint2(0u, 0u);
            if (key < LMAX)
                u = *(const uint2*)(g_qkv16 + (size_t)(b * LMAX + key) * 384 + 128 + h * 32 + (idx & 7) * 4);
            *(uint2*)&QK[row * SRW + (idx & 7) * 2] = u;
        }
        {
            int kp = tid & 31, g = tid >> 5;
            int k0 = kb0 + 2 * kp;
            uint2 a = make_uint2(0u, 0u), bb = make_uint2(0u, 0u);
            if (k0 < LMAX)
                a = *(const uint2*)(g_qkv16 + (size_t)(b * LMAX + k0) * 384 + 256 + h * 32 + g * 4);
            if (k0 + 1 < LMAX)
                bb = *(const uint2*)(g_qkv16 + (size_t)(b * LMAX + k0 + 1) * 384 + 256 + h * 32 + g * 4);
            VT[(g * 4 + 0) * VSW2 + kp] = __byte_perm(a.x, bb.x, 0x5410);
            VT[(g * 4 + 1) * VSW2 + kp] = __byte_perm(a.x, bb.x, 0x7632);
            VT[(g * 4 + 2) * VSW2 + kp] = __byte_perm(a.y, bb.y, 0x5410);
            VT[(g * 4 + 3) * VSW2 + kp] = __byte_perm(a.y, bb.y, 0x7632);
        }
        __syncthreads();

        float sf[8][4];
#pragma unroll
        for (int nt = 0; nt < 8; nt++) {
            sf[nt][0] = 0.f; sf[nt][1] = 0.f; sf[nt][2] = 0.f; sf[nt][3] = 0.f;
        }
#pragma unroll
        for (int ks = 0; ks < 2; ks++) {
            int kk = ks * 8 + lr;
#pragma unroll
            for (int nt = 0; nt < 8; nt++) {
                uint32_t b0 = QK[(nt * 8 + lq) * SRW + kk];
                uint32_t b1 = QK[(nt * 8 + lq) * SRW + kk + 4];
                mma16(sf[nt], qa[ks][0], qa[ks][1], qa[ks][2], qa[ks][3], b0, b1);
            }
        }
        float bm0 = -INFINITY, bm1 = -INFINITY;
#pragma unroll
        for (int nt = 0; nt < 8; nt++) {
            sf[nt][0] *= qs2; sf[nt][1] *= qs2;
            sf[nt][2] *= qs2; sf[nt][3] *= qs2;
            int c = kb0 + nt * 8 + lr * 2;
            if (c >= cnt) { sf[nt][0] = -1e30f; sf[nt][2] = -1e30f; }
            if (c + 1 >= cnt) { sf[nt][1] = -1e30f; sf[nt][3] = -1e30f; }
            bm0 = fmaxf(bm0, fmaxf(sf[nt][0], sf[nt][1]));
            bm1 = fmaxf(bm1, fmaxf(sf[nt][2], sf[nt][3]));
        }
        bm0 = fmaxf(bm0, __shfl_xor_sync(0xffffffffu, bm0, 1));
        bm0 = fmaxf(bm0, __shfl_xor_sync(0xffffffffu, bm0, 2));
        bm1 = fmaxf(bm1, __shfl_xor_sync(0xffffffffu, bm1, 1));
        bm1 = fmaxf(bm1, __shfl_xor_sync(0xffffffffu, bm1, 2));
        float nm0 = fmaxf(m0, bm0), nm1 = fmaxf(m1, bm1);
        float cor0 = ex2f(m0 - nm0), cor1 = ex2f(m1 - nm1);
        m0 = nm0; m1 = nm1;
        uint32_t pf01[8], pf23[8];
#pragma unroll
        for (int nt = 0; nt < 8; nt++) {
            pf01[nt] = h2ex2(f2h2(sf[nt][0] - nm0, sf[nt][1] - nm0));
            pf23[nt] = h2ex2(f2h2(sf[nt][2] - nm1, sf[nt][3] - nm1));
        }
#pragma unroll
        for (int nt = 0; nt < 4; nt++) {
            of[nt][0] *= cor0; of[nt][1] *= cor0;
            of[nt][2] *= cor1; of[nt][3] *= cor1;
        }
        float dn[4] = {0.f, 0.f, 0.f, 0.f};
#pragma unroll
        for (int ks = 0; ks < 4; ks++) {
            uint32_t a0 = pf01[2 * ks], a1 = pf23[2 * ks];
            uint32_t a2 = pf01[2 * ks + 1], a3 = pf23[2 * ks + 1];
#pragma unroll
            for (int nt = 0; nt < 4; nt++) {
                uint32_t b0 = VT[(nt * 8 + lq) * VSW2 + 8 * ks + lr];
                uint32_t b1 = VT[(nt * 8 + lq) * VSW2 + 8 * ks + lr + 4];
                mma16(of[nt], a0, a1, a2, a3, b0, b1);
            }
            mma16(dn, a0, a1, a2, a3, ones2, ones2);
        }
        den0 = den0 * cor0 + dn[0];
        den1 = den1 * cor1 + dn[2];
    }

    float i0 = 1.f / den0, i1 = 1.f / den1;
    int q_lo = qt * 128 + wid * 16 + lq, q_hi = q_lo + 8;
#pragma unroll
    for (int nt = 0; nt < 4; nt++) {
        int col = h * 32 + nt * 8 + lr * 2;
        if (q_lo < LMAX)
            *(uint32_t*)(g_attn16 + (size_t)(b * LMAX + q_lo) * DD + col) =
                f2h2(of[nt][0] * i0, of[nt][1] * i0);
        if (q_hi < LMAX)
            *(uint32_t*)(g_attn16 + (size_t)(b * LMAX + q_hi) * DD + col) =
                f2h2(of[nt][2] * i1, of[nt][3] * i1);
    }
}

// ---------------- GAT kernels (CSR, fp16 h3) ----------------
__global__ void zero_y_kernel() {
    size_t i = (size_t)blockIdx.x * blockDim.x + threadIdx.x;
    if (i < (size_t)NM * DD / 4) {
        ((float4*)g_y)[i] = make_float4(0.f, 0.f, 0.f, 0.f);
        ((uint2*)g_y16)[i] = make_uint2(0u, 0u);
    }
}

__global__ void gat_prep3(const float* __restrict__ a_src,
                          const float* __restrict__ a_dst)
{
    int gid = blockIdx.x * blockDim.x + threadIdx.x;
    int node = gid >> 5, lane = gid & 31;
    int hop = blockIdx.y;
    if (node >= NN) return;
    float s[4], d[4];
#pragma unroll
    for (int j = 0; j < 4; j++) {
        int c = j * 32 + lane;
        float hv = __half2float(g_h316[(size_t)node * 384 + hop * 128 + c]);
        s[j] = hv * a_src[hop * DD + c];
        d[j] = hv * a_dst[hop * DD + c];
    }
#pragma unroll
    for (int j = 0; j < 4; j++)
#pragma unroll
        for (int o = 16; o > 0; o >>= 1) {
            s[j] += __shfl_xor_sync(0xffffffffu, s[j], o);
            d[j] += __shfl_xor_sync(0xffffffffu, d[j], o);
        }
    if (lane == 0) {
        int idx = (node * 3 + hop) * 4;
        *(float4*)&g_als3[idx] = make_float4(s[0], s[1], s[2], s[3]);
        *(float4*)&g_ald3[idx] = make_float4(d[0], d[1], d[2], d[3]);
        g_deg[hop * NN + node] = 0;
    }
}

__global__ void deg3(const int* __restrict__ e0, const int* __restrict__ e1,
                     const int* __restrict__ e2)
{
    int hop = blockIdx.y;
    const int* ei = (hop == 0) ? e0 : (hop == 1) ? e1 : e2;
    int t = blockIdx.x * blockDim.x + threadIdx.x;
    if (t >= NITEMS) return;
    int dst = (t < NE) ? ei[NE + t] : t - NE;
    atomicAdd(&g_deg[hop * NN + dst], 1);
}

__global__ __launch_bounds__(1024) void scan3() {
    __shared__ int part[1024];
    const int hop = blockIdx.x;
    const int t = threadIdx.x;
    const int CH = (NN + 1023) / 1024;
    int beg = t * CH, end = beg + CH;
    if (end > NN) end = NN;
    int s = 0;
    for (int i = beg; i < end; i++) s += g_deg[hop * NN + i];
    part[t] = s;
    __syncthreads();
    for (int o = 1; o < 1024; o <<= 1) {
        int u = (t >= o) ? part[t - o] : 0;
        __syncthreads();
        part[t] += u;
        __syncthreads();
    }
    int run = part[t] - s;
    for (int i = beg; i < end; i++) {
        int d = g_deg[hop * NN + i];
        g_off[hop * (NN + 1) + i] = run;
        g_cur[hop * NN + i] = run;
        run += d;
    }
    if (t == 0) g_off[hop * (NN + 1) + NN] = NITEMS;
}

__global__ void edge_scat3(const int* __restrict__ e0, const int* __restrict__ e1,
                           const int* __restrict__ e2)
{
    int hop = blockIdx.y;
    const int* ei = (hop == 0) ? e0 : (hop == 1) ? e1 : e2;
    int t = blockIdx.x * blockDim.x + threadIdx.x;
    if (t >= NITEMS) return;
    int src, dst;
    if (t < NE) { src = ei[t]; dst = ei[NE + t]; }
    else { src = dst = t - NE; }
    float4 a = *(const float4*)&g_als3[(src * 3 + hop) * 4];
    float4 b = *(const float4*)&g_ald3[(dst * 3 + hop) * 4];
    float4 ew;
    ew.x = expf(leakyf(a.x + b.x, 0.2f));
    ew.y = expf(leakyf(a.y + b.y, 0.2f));
    ew.z = expf(leakyf(a.z + b.z, 0.2f));
    ew.w = expf(leakyf(a.w + b.w, 0.2f));
    int pos = atomicAdd(&g_cur[hop * NN + dst], 1);
    g_srcS[(size_t)hop * NITEMS + pos] = src;
    *(float4*)&g_ew[((size_t)hop * NITEMS + pos) * 4] = ew;
}

__global__ void aggr3(const float* __restrict__ bias) {
    int gid = blockIdx.x * blockDim.x + threadIdx.x;
    int dst = gid >> 5, lane = gid & 31;
    int hop = blockIdx.y;
    if (dst >= NN) return;
    int e0 = g_off[hop * (NN + 1) + dst];
    int e1 = g_off[hop * (NN + 1) + dst + 1];
    float4 den = make_float4(0.f, 0.f, 0.f, 0.f);
    for (int e = e0 + lane; e < e1; e += 32) {
        float4 w4 = *(const float4*)&g_ew[((size_t)hop * NITEMS + e) * 4];
        den.x += w4.x; den.y += w4.y; den.z += w4.z; den.w += w4.w;
    }
#pragma unroll
    for (int o = 16; o > 0; o >>= 1) {
        den.x += __shfl_xor_sync(0xffffffffu, den.x, o);
        den.y += __shfl_xor_sync(0xffffffffu, den.y, o);
        den.z += __shfl_xor_sync(0xffffffffu, den.z, o);
        den.w += __shfl_xor_sync(0xffffffffu, den.w, o);
    }
    float4 inv = make_float4(1.f / den.x, 1.f / den.y, 1.f / den.z, 1.f / den.w);
    float a0 = 0.f, a1 = 0.f, a2 = 0.f, a3 = 0.f;
    for (int e = e0; e < e1; e++) {
        float4 w4 = *(const float4*)&g_ew[((size_t)hop * NITEMS + e) * 4];
        int src = g_srcS[(size_t)hop * NITEMS + e];
        const __half* hs = g_h316 + (size_t)src * 384 + hop * 128;
        a0 += w4.x * inv.x * __half2float(hs[lane]);
        a1 += w4.y * inv.y * __half2float(hs[32 + lane]);
        a2 += w4.z * inv.z * __half2float(hs[64 + lane]);
        a3 += w4.w * inv.w * __half2float(hs[96 + lane]);
    }
    __half* gd = g_gout316 + (size_t)dst * 384 + hop * 128;
    const float* bb = bias + hop * 128;
    gd[lane]      = __float2half(a0 + bb[lane]);
    gd[32 + lane] = __float2half(a1 + bb[32 + lane]);
    gd[64 + lane] = __float2half(a2 + bb[64 + lane]);
    gd[96 + lane] = __float2half(a3 + bb[96 + lane]);
}

// ---------------- fused sequence-position kernel ----------------
__global__ __launch_bounds__(256) void seq_kernel(const int* __restrict__ genre) {
    __shared__ int ch[NCHUNK * NG];
    int tid = threadIdx.x;
    if (tid < NCHUNK) {
        for (int g = 0; g < NG; g++) ch[tid * NG + g] = 0;
        int base = tid * 128;
        int end = base + 128; if (end > NM) end = NM;
        for (int i = base; i < end; i++) ch[tid * NG + genre[i]]++;
    }
    __syncthreads();
    if (tid < NG) {
        int run = 0;
        for (int c = 0; c < NCHUNK; c++) {
            int t = ch[c * NG + tid];
            ch[c * NG + tid] = run;
            run += t;
        }
        g_cnt[tid] = run;
    }
    __syncthreads();
    if (tid < NCHUNK) {
        int base = tid * 128;
        int end = base + 128; if (end > NM) end = NM;
        for (int i = base; i < end; i++) {
            int g = genre[i];
            g_pos[i] = ch[tid * NG + g]++;
        }
    }
}

__global__ void gather_kernel(const int* __restrict__ movie_idx, const int* __restrict__ genre,
                              const float* __restrict__ src)
{
    int t = blockIdx.x * blockDim.x + threadIdx.x;
    if (t >= NM * 32) return;
    int i = t >> 5, c4 = (t & 31) * 4;
    float4 v = *(const float4*)&src[(size_t)movie_idx[i] * DD + c4];
    uint2 h2 = make_uint2(f2h2(v.x, v.y), f2h2(v.z, v.w));
    *(uint2*)(g_xm16 + (size_t)i * DD + c4) = h2;
    int row = genre[i] * LMAX + g_pos[i];
    *(float4*)&g_y[(size_t)row * DD + c4] = v;
    *(uint2*)(g_y16 + (size_t)row * DD + c4) = h2;
}

// ---------------- fused pool + pe ----------------
__global__ void pool_pe(const float* __restrict__ fus_w) {
    __shared__ float pr[DD];
    int g = blockIdx.x, d = threadIdx.x;
    int cnt = g_cnt[g];
    float s = 0.f;
    for (int t = 0; t < cnt; t++) s += g_y[(size_t)(g * LMAX + t) * DD + d];
    pr[d] = s / fmaxf((float)cnt, 1.f);
    __syncthreads();
    float acc = 0.f;
    for (int k = 0; k < DD; k++)
        acc += pr[k] * fus_w[d * 256 + 128 + k];
    g_pe[g * DD + d] = acc;
}

// ---------------- launch ----------------
extern "C" void kernel_launch(void* const* d_in, const int* in_sizes, int n_in,
                              void* d_out, int out_size)
{
    const float* x        = (const float*)d_in[0];
    const int*   e0       = (const int*)d_in[1];
    const int*   e1       = (const int*)d_in[2];
    const int*   e2       = (const int*)d_in[3];
    const int*   movie_idx = (const int*)d_in[4];
    const int*   genre     = (const int*)d_in[5];
    const float* gat_W    = (const float*)d_in[6];
    const float* att_src  = (const float*)d_in[7];
    const float* att_dst  = (const float*)d_in[8];
    const float* gat_bias = (const float*)d_in[9];
    const float* dec_W    = (const float*)d_in[10];
    const float* dec_b    = (const float*)d_in[11];
    const float* qkv_w    = (const float*)d_in[12];
    const float* qkv_b    = (const float*)d_in[13];
    const float* out_w    = (const float*)d_in[14];
    const float* out_b    = (const float*)d_in[15];
    const float* ln1_g    = (const float*)d_in[16];
    const float* ln1_b    = (const float*)d_in[17];
    const float* ln2_g    = (const float*)d_in[18];
    const float* ln2_b    = (const float*)d_in[19];
    const float* ffn_w1   = (const float*)d_in[20];
    const float* ffn_b1   = (const float*)d_in[21];
    const float* ffn_w2   = (const float*)d_in[22];
    const float* ffn_b2   = (const float*)d_in[23];
    const float* fus_w    = (const float*)d_in[24];
    const float* fus_b    = (const float*)d_in[25];
    float* out = (float*)d_out;

    float *p_y;
    __half *p_x16, *p_h316, *p_gout316, *p_y16, *p_qkv16, *p_attn16, *p_ffn16, *p_xm16;
    __half *p_gatW16, *p_decW16, *p_qkvW16, *p_outW16, *p_fw116, *p_fw216, *p_fusW16;
    cudaGetSymbolAddress((void**)&p_y,      g_y);
    cudaGetSymbolAddress((void**)&p_x16,    g_x16);
    cudaGetSymbolAddress((void**)&p_h316,   g_h316);
    cudaGetSymbolAddress((void**)&p_gout316, g_gout316);
    cudaGetSymbolAddress((void**)&p_y16,    g_y16);
    cudaGetSymbolAddress((void**)&p_qkv16,  g_qkv16);
    cudaGetSymbolAddress((void**)&p_attn16, g_attn16);
    cudaGetSymbolAddress((void**)&p_ffn16,  g_ffn16);
    cudaGetSymbolAddress((void**)&p_xm16,   g_xm16);
    cudaGetSymbolAddress((void**)&p_gatW16, g_gatW16);
    cudaGetSymbolAddress((void**)&p_decW16, g_decW16);
    cudaGetSymbolAddress((void**)&p_qkvW16, g_qkvW16);
    cudaGetSymbolAddress((void**)&p_outW16, g_outW16);
    cudaGetSymbolAddress((void**)&p_fw116,  g_fw116);
    cudaGetSymbolAddress((void**)&p_fw216,  g_fw216);
    cudaGetSymbolAddress((void**)&p_fusW16, g_fusW16);

    const int GSMEM = 4 * TBUF * 4;          // 40960 B
    const int LNSMEM = 128 * LNS * 4;        // 67584 B
    cudaFuncSetAttribute(gemm_mma, cudaFuncAttributeMaxDynamicSharedMemorySize, GSMEM);
    cudaFuncSetAttribute(gemm_mma_h, cudaFuncAttributeMaxDynamicSharedMemorySize, GSMEM);
    cudaFuncSetAttribute(gemm_dec, cudaFuncAttributeMaxDynamicSharedMemorySize, GSMEM);
    cudaFuncSetAttribute(gemm_fuse, cudaFuncAttributeMaxDynamicSharedMemorySize, GSMEM);
    cudaFuncSetAttribute(gemm_ln, cudaFuncAttributeMaxDynamicSharedMemorySize, LNSMEM);

    const int MTN = (NN + 127) / 128;  // 391
    const int MT  = (NM + 127) / 128;  // 160

    // -------- one-shot fp16 conversions (single launch) --------
    F2HBatch fb2;
    fb2.src[0] = x;      fb2.dst[0] = p_x16;    fb2.n4[0] = NN * DD / 4;
    fb2.src[1] = gat_W;  fb2.dst[1] = p_gatW16; fb2.n4[1] = 3 * DD * DD / 4;
    fb2.src[2] = dec_W;  fb2.dst[2] = p_decW16; fb2.n4[2] = 3 * DD * DD / 4;
    fb2.src[3] = qkv_w;  fb2.dst[3] = p_qkvW16; fb2.n4[3] = NL * 3 * DD * DD / 4;
    fb2.src[4] = out_w;  fb2.dst[4] = p_outW16; fb2.n4[4] = NL * DD * DD / 4;
    fb2.src[5] = ffn_w1; fb2.dst[5] = p_fw116;  fb2.n4[5] = NL * FFD * DD / 4;
    fb2.src[6] = ffn_w2; fb2.dst[6] = p_fw216;  fb2.n4[6] = NL * DD * FFD / 4;
    fb2.src[7] = fus_w;  fb2.dst[7] = p_fusW16; fb2.n4[7] = DD * 256 / 4;
    f2h_multi<<<dim3(592, 8), 256>>>(fb2);

    // -------- GAT --------
    gemm_mma<<<dim3(3, MTN), 256, GSMEM>>>(p_x16, p_gatW16, nullptr, nullptr, p_h316,
                                           NN, 384, DD, DD, DD, 3);
    gat_prep3<<<dim3((NN * 32 + 255) / 256, 3), 256>>>(att_src, att_dst);
    deg3<<<dim3((NITEMS + 255) / 256, 3), 256>>>(e0, e1, e2);
    scan3<<<3, 1024>>>();
    edge_scat3<<<dim3((NITEMS + 255) / 256, 3), 256>>>(e0, e1, e2);
    aggr3<<<dim3((NN * 32 + 255) / 256, 3), 256>>>(gat_bias);
    gemm_dec<<<dim3(1, MTN), 256, GSMEM>>>(p_gout316, p_decW16, dec_b, out, NN);

    // -------- build genre sequences --------
    seq_kernel<<<1, 256>>>(genre);
    zero_y_kernel<<<(NM * DD / 4 + 255) / 256, 256>>>();
    gather_kernel<<<(NM * 32 + 255) / 256, 256>>>(movie_idx, genre, out);

    // -------- transformer (4 layers; qkv + FFN1 use fp16 accumulators) --------
    for (int l = 0; l < NL; l++) {
        gemm_mma_h<<<dim3(3 * DD / 128, MT), 256, GSMEM>>>(
            p_y16, p_qkvW16 + (size_t)l * 3 * DD * DD, qkv_b + l * 3 * DD,
            p_qkv16, NM, 3 * DD, DD, DD, DD, 3);
        attn_tc<<<dim3((LMAX + 127) / 128, NHEADS, NG), 256>>>();
        gemm_ln<<<dim3(1, MT), 256, LNSMEM>>>(
            p_attn16, p_outW16 + (size_t)l * DD * DD, out_b + l * DD,
            ln1_g + l * DD, ln1_b + l * DD, p_y, p_y16, NM, DD);
        gemm_mma_h<<<dim3(FFD / 128, MT), 256, GSMEM>>>(
            p_y16, p_fw116 + (size_t)l * FFD * DD, ffn_b1 + l * FFD,
            p_ffn16, NM, FFD, DD, DD, DD, 4);
        gemm_ln<<<dim3(1, MT), 256, LNSMEM>>>(
            p_ffn16, p_fw216 + (size_t)l * DD * FFD, ffn_b2 + l * DD,
            ln2_g + l * DD, ln2_b + l * DD, p_y, p_y16, NM, FFD);
    }

    // -------- pool + fused final GEMM --------
    pool_pe<<<NG, DD>>>(fus_w);
    gemm_fuse<<<dim3(1, MT), 256, GSMEM>>>(p_xm16, p_fusW16, movie_idx, genre,
                                           fus_b, out, NM);
}

// round 17
// speedup vs baseline: 1.0294x; 1.0294x over previous
#include <cuda_runtime.h>
#include <cuda_fp16.h>
#include <math.h>
#include <stdint.h>

#define NN 50000
#define NE 400000
#define DD 128
#define NM 20400
#define NG 30
#define LMAX 680
#define NHEADS 4
#define NL 4
#define FFD 2048
#define NCHUNK 160   // ceil(20400/128)
#define NITEMS (NE + NN)

// ---------------- scratch (device globals; no runtime allocation) ----------------
__device__ __align__(16) float  g_als3[NN * 3 * NHEADS];
__device__ __align__(16) float  g_ald3[NN * 3 * NHEADS];
__device__ __align__(16) float  g_ew[(size_t)3 * NITEMS * NHEADS];
__device__ int g_srcS[(size_t)3 * NITEMS];
__device__ int g_deg[3 * NN];
__device__ int g_off[3 * (NN + 1)];
__device__ int g_cur[3 * NN];
__device__ __align__(16) float  g_y[(size_t)NM * DD];
__device__ __align__(16) float  g_pe[NG * DD];
__device__ int g_pos[NM];
__device__ int g_cnt[NG];
// fp16 shadows / intermediates
__device__ __align__(16) __half g_x16[(size_t)NN * DD];
__device__ __align__(16) __half g_h316[(size_t)NN * 384];
__device__ __align__(16) __half g_gout316[(size_t)NN * 384];
__device__ __align__(16) __half g_y16[(size_t)NM * DD];
__device__ __align__(16) __half g_qkv16[(size_t)NM * 3 * DD];
__device__ __align__(16) __half g_attn16[(size_t)NM * DD];
__device__ __align__(16) __half g_ffn16[(size_t)NM * FFD];
__device__ __align__(16) __half g_xm16[(size_t)NM * DD];
// fp16 weights
__device__ __align__(16) __half g_gatW16[3 * DD * DD];
__device__ __align__(16) __half g_decW16[3 * DD * DD];
__device__ __align__(16) __half g_qkvW16[NL * 3 * DD * DD];
__device__ __align__(16) __half g_outW16[NL * DD * DD];
__device__ __align__(16) __half g_fw116[(size_t)NL * FFD * DD];
__device__ __align__(16) __half g_fw216[(size_t)NL * DD * FFD];
__device__ __align__(16) __half g_fusW16[DD * 256];

// ---------------- small helpers ----------------
__device__ __forceinline__ float leakyf(float x, float s) { return x >= 0.f ? x : s * x; }

__device__ __forceinline__ uint32_t f2h2(float lo, float hi) {
    uint32_t r;
    asm("cvt.rn.f16x2.f32 %0, %1, %2;" : "=r"(r) : "f"(hi), "f"(lo));
    return r;
}

__device__ __forceinline__ uint32_t h2ex2(uint32_t x) {
    uint32_t r;
    asm("ex2.approx.f16x2 %0, %1;" : "=r"(r) : "r"(x));
    return r;
}

__device__ __forceinline__ float ex2f(float x) {
    float r;
    asm("ex2.approx.f32 %0, %1;" : "=f"(r) : "f"(x));
    return r;
}

__device__ __forceinline__ uint32_t smem_u32(const void* p) {
    uint32_t a;
    asm("{ .reg .u64 t; cvta.to.shared.u64 t, %1; cvt.u32.u64 %0, t; }" : "=r"(a) : "l"(p));
    return a;
}

__device__ __forceinline__ void mma16(float* c, uint32_t a0, uint32_t a1, uint32_t a2,
                                      uint32_t a3, uint32_t b0, uint32_t b1) {
    asm volatile(
        "mma.sync.aligned.m16n8k16.row.col.f32.f16.f16.f32 "
        "{%0,%1,%2,%3}, {%4,%5,%6,%7}, {%8,%9}, {%0,%1,%2,%3};"
        : "+f"(c[0]), "+f"(c[1]), "+f"(c[2]), "+f"(c[3])
        : "r"(a0), "r"(a1), "r"(a2), "r"(a3), "r"(b0), "r"(b1));
}

__device__ __forceinline__ void ldsm4(uint32_t* r, uint32_t addr) {
    asm volatile("ldmatrix.sync.aligned.m8n8.x4.shared.b16 {%0,%1,%2,%3}, [%4];"
                 : "=r"(r[0]), "=r"(r[1]), "=r"(r[2]), "=r"(r[3]) : "r"(addr));
}

// ---------------- batched float -> half conversion (one launch) ----------------
struct F2HBatch {
    const float* src[8];
    __half* dst[8];
    int n4[8];
};
__global__ void f2h_multi(F2HBatch b) {
    int a = blockIdx.y;
    int n4 = b.n4[a];
    const float* s = b.src[a];
    __half* d = b.dst[a];
    for (int i = blockIdx.x * blockDim.x + threadIdx.x; i < n4; i += gridDim.x * blockDim.x) {
        float4 v = ((const float4*)s)[i];
        uint2 u;
        u.x = f2h2(v.x, v.y);
        u.y = f2h2(v.z, v.w);
        ((uint2*)d)[i] = u;
    }
}

#define SRW 20
#define TBUF (128 * SRW)

#define FRAG_SETUP                                                  \
    const int tid = threadIdx.x;                                    \
    const int wid = tid >> 5, lane = tid & 31;                      \
    const int wm = wid & 1, wn = wid >> 1;                          \
    const int lq = lane >> 2, lr = lane & 3;                        \
    const int rr = lane & 7;                                        \
    const int aRow = wm * 64 + rr + ((lane >> 3) & 1) * 8;          \
    const int aColW = ((lane >> 4) & 1) * 4;                        \
    const int bRow = wn * 32 + rr + ((lane >> 4) & 1) * 8;          \
    const int bColW = ((lane >> 3) & 1) * 4;                        \
    const int s_row = tid >> 2;                                     \
    const int s_c = tid & 3;

#define STS_CHUNK(Ad, Bd)                                           \
    {                                                               \
        _Pragma("unroll")                                           \
        for (int it = 0; it < 2; it++) {                            \
            int row = it * 64 + s_row;                              \
            *(uint4*)&(Ad)[row * SRW + s_c * 4] = pa[it];           \
            *(uint4*)&(Bd)[row * SRW + s_c * 4] = pb[it];           \
        }                                                           \
    }
#define COMPUTE_KS(AsAddr, BsAddr, KS)                                                 \
    {                                                                                  \
        uint32_t bq[2][4];                                                             \
        _Pragma("unroll")                                                              \
        for (int ntp = 0; ntp < 2; ntp++)                                              \
            ldsm4(bq[ntp], (BsAddr) + (((bRow + ntp * 16) * SRW) + (KS) * 8 + bColW) * 4); \
        _Pragma("unroll")                                                              \
        for (int mt = 0; mt < 4; mt++) {                                               \
            uint32_t aq[4];                                                            \
            ldsm4(aq, (AsAddr) + (((aRow + mt * 16) * SRW) + (KS) * 8 + aColW) * 4);   \
            _Pragma("unroll")                                                          \
            for (int nt = 0; nt < 4; nt++)                                             \
                mma16(acc[mt][nt], aq[0], aq[1], aq[2], aq[3],                         \
                      bq[nt >> 1][(nt & 1) * 2 + 0], bq[nt >> 1][(nt & 1) * 2 + 1]);   \
        }                                                                              \
    }

#define GEMM_BODY(LDGMACRO, NCHUNKS)                                                   \
    uint32_t* A0 = sm;                                                                 \
    uint32_t* B0 = sm + TBUF;                                                          \
    uint32_t* A1 = sm + 2 * TBUF;                                                      \
    uint32_t* B1 = sm + 3 * TBUF;                                                      \
    const uint32_t sb = smem_u32(sm);                                                  \
    const uint32_t aAddr0 = sb, bAddr0 = sb + TBUF * 4;                                \
    const uint32_t aAddr1 = sb + 2 * TBUF * 4, bAddr1 = sb + 3 * TBUF * 4;             \
    LDGMACRO(0);                                                                       \
    STS_CHUNK(A0, B0);                                                                 \
    if ((NCHUNKS) > 1) LDGMACRO(1);                                                    \
    __syncthreads();                                                                   \
    for (int c = 0; c < (NCHUNKS); c++) {                                              \
        uint32_t aA = (c & 1) ? aAddr1 : aAddr0;                                       \
        uint32_t bA = (c & 1) ? bAddr1 : bAddr0;                                       \
        uint32_t* Asn = (c & 1) ? A0 : A1;                                             \
        uint32_t* Bsn = (c & 1) ? B0 : B1;                                             \
        COMPUTE_KS(aA, bA, 0);                                                         \
        if (c + 1 < (NCHUNKS)) STS_CHUNK(Asn, Bsn);                                    \
        COMPUTE_KS(aA, bA, 1);                                                         \
        if (c + 2 < (NCHUNKS)) LDGMACRO(c + 2);                                        \
        __syncthreads();                                                               \
    }

// ---------------- pipelined fp16 mma GEMM ----------------
// epi: 0 = fp32 store(+bias), 3 = fp16 store -> C16, 4 = fp16 relu -> C16
__global__ __launch_bounds__(256) void gemm_mma(
    const __half* __restrict__ A, const __half* __restrict__ B,
    const float* __restrict__ bias, float* __restrict__ C, __half* __restrict__ C16,
    int M, int N, int K, int lda, int ldb, int epi)
{
    extern __shared__ uint32_t sm[];
    FRAG_SETUP
    const int row0 = blockIdx.y * 128, col0 = blockIdx.x * 128;

    float acc[4][4][4];
#pragma unroll
    for (int i = 0; i < 4; i++)
#pragma unroll
        for (int j = 0; j < 4; j++) {
            acc[i][j][0] = 0.f; acc[i][j][1] = 0.f;
            acc[i][j][2] = 0.f; acc[i][j][3] = 0.f;
        }
    const int nC = K >> 5;
    uint4 pa[2], pb[2];

#define LDG_CHUNK(cc)                                                                  \
    {                                                                                  \
        int k0 = (cc) << 5;                                                            \
        _Pragma("unroll")                                                              \
        for (int it = 0; it < 2; it++) {                                               \
            int row = it * 64 + s_row;                                                 \
            int gr = row0 + row;                                                       \
            pa[it] = make_uint4(0u, 0u, 0u, 0u);                                       \
            if (gr < M) pa[it] = *(const uint4*)(A + (size_t)gr * lda + k0 + s_c * 8); \
            pb[it] = *(const uint4*)(B + (size_t)(col0 + row) * ldb + k0 + s_c * 8);   \
        }                                                                              \
    }

    GEMM_BODY(LDG_CHUNK, nC)

    const int rbase = row0 + wm * 64;
    const int cbase = col0 + wn * 32;
#pragma unroll
    for (int mt = 0; mt < 4; mt++) {
        int r0 = rbase + mt * 16 + lq;
#pragma unroll
        for (int half = 0; half < 2; half++) {
            int r = r0 + half * 8;
            if (r < M) {
#pragma unroll
                for (int nt = 0; nt < 4; nt++) {
                    int c = cbase + nt * 8 + lr * 2;
                    float v0 = acc[mt][nt][half * 2 + 0];
                    float v1 = acc[mt][nt][half * 2 + 1];
                    if (bias) { v0 += bias[c]; v1 += bias[c + 1]; }
                    if (epi == 0) {
                        *(float2*)(C + (size_t)r * N + c) = make_float2(v0, v1);
                    } else if (epi == 3) {
                        *(uint32_t*)(C16 + (size_t)r * N + c) = f2h2(v0, v1);
                    } else {
                        *(uint32_t*)(C16 + (size_t)r * N + c) =
                            f2h2(fmaxf(v0, 0.f), fmaxf(v1, 0.f));
                    }
                }
            }
        }
    }
}

// ---------------- final fusion GEMM ----------------
__global__ __launch_bounds__(256) void gemm_fuse(
    const __half* __restrict__ A, const __half* __restrict__ B,
    const int* __restrict__ midx, const int* __restrict__ genre,
    const float* __restrict__ fb, float* __restrict__ out, int M)
{
    extern __shared__ uint32_t sm[];
    FRAG_SETUP
    const int row0 = blockIdx.y * 128;
    const int col0 = 0;
    const int ldb = 256;

    float acc[4][4][4];
#pragma unroll
    for (int i = 0; i < 4; i++)
#pragma unroll
        for (int j = 0; j < 4; j++) {
            acc[i][j][0] = 0.f; acc[i][j][1] = 0.f;
            acc[i][j][2] = 0.f; acc[i][j][3] = 0.f;
        }
    uint4 pa[2], pb[2];

#define LDG_FUSE(cc)                                                                   \
    {                                                                                  \
        int k0 = (cc) << 5;                                                            \
        _Pragma("unroll")                                                              \
        for (int it = 0; it < 2; it++) {                                               \
            int row = it * 64 + s_row;                                                 \
            int gr = row0 + row;                                                       \
            pa[it] = make_uint4(0u, 0u, 0u, 0u);                                       \
            if (gr < M) pa[it] = *(const uint4*)(A + (size_t)gr * DD + k0 + s_c * 8);  \
            pb[it] = *(const uint4*)(B + (size_t)(col0 + row) * ldb + k0 + s_c * 8);   \
        }                                                                              \
    }

    GEMM_BODY(LDG_FUSE, 4)

    const int rbase = row0 + wm * 64;
    const int cbase = wn * 32;
#pragma unroll
    for (int mt = 0; mt < 4; mt++) {
        int r0 = rbase + mt * 16 + lq;
#pragma unroll
        for (int half = 0; half < 2; half++) {
            int r = r0 + half * 8;
            if (r < M) {
                int gidx = genre[r];
                int orow = midx[r];
#pragma unroll
                for (int nt = 0; nt < 4; nt++) {
                    int c = cbase + nt * 8 + lr * 2;
                    float v0 = acc[mt][nt][half * 2 + 0] + g_pe[gidx * DD + c] + fb[c];
                    float v1 = acc[mt][nt][half * 2 + 1] + g_pe[gidx * DD + c + 1] + fb[c + 1];
                    *(float2*)(out + (size_t)orow * DD + c) =
                        make_float2(leakyf(v0, 0.01f), leakyf(v1, 0.01f));
                }
            }
        }
    }
}

// ---------------- GEMM (N=128) fused with residual LayerNorm ----------------
#define LNS 132
__global__ __launch_bounds__(256) void gemm_ln(
    const __half* __restrict__ A, const __half* __restrict__ B,
    const float* __restrict__ bias,
    const float* __restrict__ gam, const float* __restrict__ bet,
    float* __restrict__ y, __half* __restrict__ y16, int M, int K)
{
    extern __shared__ uint32_t sm[];
    FRAG_SETUP
    const int row0 = blockIdx.y * 128;
    const int col0 = 0;

    float acc[4][4][4];
#pragma unroll
    for (int i = 0; i < 4; i++)
#pragma unroll
        for (int j = 0; j < 4; j++) {
            acc[i][j][0] = 0.f; acc[i][j][1] = 0.f;
            acc[i][j][2] = 0.f; acc[i][j][3] = 0.f;
        }
    const int nC = K >> 5;
    uint4 pa[2], pb[2];

#define LDG_LN(cc)                                                                     \
    {                                                                                  \
        int k0 = (cc) << 5;                                                            \
        _Pragma("unroll")                                                              \
        for (int it = 0; it < 2; it++) {                                               \
            int row = it * 64 + s_row;                                                 \
            int gr = row0 + row;                                                       \
            pa[it] = make_uint4(0u, 0u, 0u, 0u);                                       \
            if (gr < M) pa[it] = *(const uint4*)(A + (size_t)gr * K + k0 + s_c * 8);   \
            pb[it] = *(const uint4*)(B + (size_t)(col0 + row) * K + k0 + s_c * 8);     \
        }                                                                              \
    }

    GEMM_BODY(LDG_LN, nC)

    float* stg = (float*)sm;
    const int rbl = wm * 64;
    const int cb = wn * 32;
#pragma unroll
    for (int mt = 0; mt < 4; mt++) {
#pragma unroll
        for (int half = 0; half < 2; half++) {
            int rl = rbl + mt * 16 + lq + half * 8;
#pragma unroll
            for (int nt = 0; nt < 4; nt++) {
                int c = cb + nt * 8 + lr * 2;
                float v0 = acc[mt][nt][half * 2 + 0] + bias[c];
                float v1 = acc[mt][nt][half * 2 + 1] + bias[c + 1];
                *(float2*)&stg[rl * LNS + c] = make_float2(v0, v1);
            }
        }
    }
    __syncthreads();

    float4 gg = *(const float4*)(gam + lane * 4);
    float4 bb = *(const float4*)(bet + lane * 4);
    for (int rw = 0; rw < 16; rw++) {
        int rl = wid * 16 + rw;
        int r = row0 + rl;
        if (r >= M) break;
        size_t off = (size_t)r * DD + lane * 4;
        float4 v = *(float4*)(y + off);
        float4 t4 = *(float4*)&stg[rl * LNS + lane * 4];
        v.x += t4.x; v.y += t4.y; v.z += t4.z; v.w += t4.w;
        float s = v.x + v.y + v.z + v.w;
#pragma unroll
        for (int o = 16; o > 0; o >>= 1) s += __shfl_xor_sync(0xffffffffu, s, o);
        float mean = s * (1.f / DD);
        float dx = v.x - mean, dy = v.y - mean, dz = v.z - mean, dw = v.w - mean;
        float ss = dx * dx + dy * dy + dz * dz + dw * dw;
#pragma unroll
        for (int o = 16; o > 0; o >>= 1) ss += __shfl_xor_sync(0xffffffffu, ss, o);
        float inv = rsqrtf(ss * (1.f / DD) + 1e-5f);
        v.x = dx * inv * gg.x + bb.x;
        v.y = dy * inv * gg.y + bb.y;
        v.z = dz * inv * gg.z + bb.z;
        v.w = dw * inv * gg.w + bb.w;
        *(float4*)(y + off) = v;
        *(uint2*)(y16 + off) = make_uint2(f2h2(v.x, v.y), f2h2(v.z, v.w));
    }
}

// ---------------- fused 3-hop decoder GEMM ----------------
__global__ __launch_bounds__(256) void gemm_dec(
    const __half* __restrict__ A, const __half* __restrict__ B,
    const float* __restrict__ bias, float* __restrict__ Cout, int M)
{
    extern __shared__ uint32_t sm[];
    FRAG_SETUP
    const int row0 = blockIdx.y * 128;
    const float scales[3] = {1.f, 0.90483741803596f, 0.81873075307798f};

    float acc[4][4][4], acc2[4][4][4];
#pragma unroll
    for (int i = 0; i < 4; i++)
#pragma unroll
        for (int j = 0; j < 4; j++)
#pragma unroll
            for (int k = 0; k < 4; k++) { acc[i][j][k] = 0.f; acc2[i][j][k] = 0.f; }

    uint4 pa[2], pb[2];
#define LDG_DEC(cc)                                                                    \
    {                                                                                  \
        int k0 = (cc) << 5;                                                            \
        int hop = (cc) >> 2, kb = ((cc) & 3) << 5;                                     \
        _Pragma("unroll")                                                              \
        for (int it = 0; it < 2; it++) {                                               \
            int row = it * 64 + s_row;                                                 \
            int gr = row0 + row;                                                       \
            pa[it] = make_uint4(0u, 0u, 0u, 0u);                                       \
            if (gr < M) pa[it] = *(const uint4*)(A + (size_t)gr * 384 + k0 + s_c * 8); \
            pb[it] = *(const uint4*)(B + (size_t)hop * 16384 + (size_t)row * 128 + kb + s_c * 8); \
        }                                                                              \
    }

    uint32_t* A0 = sm;
    uint32_t* B0 = sm + TBUF;
    uint32_t* A1 = sm + 2 * TBUF;
    uint32_t* B1 = sm + 3 * TBUF;
    const uint32_t sb = smem_u32(sm);
    const uint32_t aAddr0 = sb, bAddr0 = sb + TBUF * 4;
    const uint32_t aAddr1 = sb + 2 * TBUF * 4, bAddr1 = sb + 3 * TBUF * 4;
    const int cbase = wn * 32;

    LDG_DEC(0);
    STS_CHUNK(A0, B0);
    LDG_DEC(1);
    __syncthreads();

    for (int c = 0; c < 12; c++) {
        uint32_t aA = (c & 1) ? aAddr1 : aAddr0;
        uint32_t bA = (c & 1) ? bAddr1 : bAddr0;
        uint32_t* Asn = (c & 1) ? A0 : A1;
        uint32_t* Bsn = (c & 1) ? B0 : B1;
        COMPUTE_KS(aA, bA, 0);
        if (c + 1 < 12) STS_CHUNK(Asn, Bsn);
        COMPUTE_KS(aA, bA, 1);
        if (c + 2 < 12) LDG_DEC(c + 2);
        __syncthreads();
        if ((c & 3) == 3) {
            int hop = c >> 2;
            float sc = scales[hop];
#pragma unroll
            for (int nt = 0; nt < 4; nt++) {
                int col = cbase + nt * 8 + lr * 2;
                float b0 = bias[hop * 128 + col];
                float b1 = bias[hop * 128 + col + 1];
#pragma unroll
                for (int mt = 0; mt < 4; mt++) {
                    acc2[mt][nt][0] += sc * leakyf(acc[mt][nt][0] + b0, 0.01f);
                    acc2[mt][nt][1] += sc * leakyf(acc[mt][nt][1] + b1, 0.01f);
                    acc2[mt][nt][2] += sc * leakyf(acc[mt][nt][2] + b0, 0.01f);
                    acc2[mt][nt][3] += sc * leakyf(acc[mt][nt][3] + b1, 0.01f);
                    acc[mt][nt][0] = 0.f; acc[mt][nt][1] = 0.f;
                    acc[mt][nt][2] = 0.f; acc[mt][nt][3] = 0.f;
                }
            }
        }
    }

    const int rbase = row0 + wm * 64;
#pragma unroll
    for (int mt = 0; mt < 4; mt++) {
        int r0 = rbase + mt * 16 + lq;
#pragma unroll
        for (int half = 0; half < 2; half++) {
            int r = r0 + half * 8;
            if (r < M) {
#pragma unroll
                for (int nt = 0; nt < 4; nt++) {
                    int col = cbase + nt * 8 + lr * 2;
                    *(float2*)(Cout + (size_t)r * DD + col) =
                        make_float2(acc2[mt][nt][half * 2 + 0], acc2[mt][nt][half * 2 + 1]);
                }
            }
        }
    }
}

// ---------------- fp16 tensor-core flash attention (KB=64, 2 blocks/SM) ----------------
#define VSW2 36
__global__ __launch_bounds__(256, 2) void attn_tc() {
    __shared__ uint32_t QK[128 * SRW];
    __shared__ uint32_t VT[32 * VSW2];
    const int b = blockIdx.z, h = blockIdx.y, qt = blockIdx.x;
    const int cnt = g_cnt[b];
    const int tid = threadIdx.x, wid = tid >> 5, lane = tid & 31;
    const int lq = lane >> 2, lr = lane & 3;
    const float qs2 = 0.2550181731927341f;   // (1/sqrt(32)) * log2(e)
    const uint32_t ones2 = 0x3C003C00u;

#pragma unroll
    for (int it = 0; it < 4; it++) {
        int idx = it * 256 + tid;
        int row = idx >> 3;
        int q = qt * 128 + row;
        uint2 u = make_uint2(0u, 0u);
        if (q < LMAX)
            u = *(const uint2*)(g_qkv16 + (size_t)(b * LMAX + q) * 384 + h * 32 + (idx & 7) * 4);
        *(uint2*)&QK[row * SRW + (idx & 7) * 2] = u;
    }
    __syncthreads();
    uint32_t qa[2][4];
    {
        int r = wid * 16 + lq;
#pragma unroll
        for (int ks = 0; ks < 2; ks++) {
            int kb = ks * 8 + lr;
            qa[ks][0] = QK[r * SRW + kb];
            qa[ks][1] = QK[(r + 8) * SRW + kb];
            qa[ks][2] = QK[r * SRW + kb + 4];
            qa[ks][3] = QK[(r + 8) * SRW + kb + 4];
        }
    }

    float m0 = -INFINITY, m1 = -INFINITY, den0 = 0.f, den1 = 0.f;
    float of[4][4];
#pragma unroll
    for (int nt = 0; nt < 4; nt++) {
        of[nt][0] = 0.f; of[nt][1] = 0.f; of[nt][2] = 0.f; of[nt][3] = 0.f;
    }

    for (int kb0 = 0; kb0 < LMAX; kb0 += 64) {
        __syncthreads();
#pragma unroll
        for (int it = 0; it < 2; it++) {
            int idx = it * 256 + tid;
            int row = idx >> 3;
            int key = kb0 + row;
            uint2 u = make_uint2(0u, 0u);
            if (key < LMAX)
                u = *(const uint2*)(g_qkv16 + (size_t)(b * LMAX + key) * 384 + 128 + h * 32 + (idx & 7) * 4);
            *(uint2*)&QK[row * SRW + (idx & 7) * 2] = u;
        }
        {
            int kp = tid & 31, g = tid >> 5;
            int k0 = kb0 + 2 * kp;
            uint2 a = make_uint2(0u, 0u), bb = make_uint2(0u, 0u);
            if (k0 < LMAX)
                a = *(const uint2*)(g_qkv16 + (size_t)(b * LMAX + k0) * 384 + 256 + h * 32 + g * 4);
            if (k0 + 1 < LMAX)
                bb = *(const uint2*)(g_qkv16 + (size_t)(b * LMAX + k0 + 1) * 384 + 256 + h * 32 + g * 4);
            VT[(g * 4 + 0) * VSW2 + kp] = __byte_perm(a.x, bb.x, 0x5410);
            VT[(g * 4 + 1) * VSW2 + kp] = __byte_perm(a.x, bb.x, 0x7632);
            VT[(g * 4 + 2) * VSW2 + kp] = __byte_perm(a.y, bb.y, 0x5410);
            VT[(g * 4 + 3) * VSW2 + kp] = __byte_perm(a.y, bb.y, 0x7632);
        }
        __syncthreads();

        float sf[8][4];
#pragma unroll
        for (int nt = 0; nt < 8; nt++) {
            sf[nt][0] = 0.f; sf[nt][1] = 0.f; sf[nt][2] = 0.f; sf[nt][3] = 0.f;
        }
#pragma unroll
        for (int ks = 0; ks < 2; ks++) {
            int kk = ks * 8 + lr;
#pragma unroll
            for (int nt = 0; nt < 8; nt++) {
                uint32_t b0 = QK[(nt * 8 + lq) * SRW + kk];
                uint32_t b1 = QK[(nt * 8 + lq) * SRW + kk + 4];
                mma16(sf[nt], qa[ks][0], qa[ks][1], qa[ks][2], qa[ks][3], b0, b1);
            }
        }
        float bm0 = -INFINITY, bm1 = -INFINITY;
#pragma unroll
        for (int nt = 0; nt < 8; nt++) {
            sf[nt][0] *= qs2; sf[nt][1] *= qs2;
            sf[nt][2] *= qs2; sf[nt][3] *= qs2;
            int c = kb0 + nt * 8 + lr * 2;
            if (c >= cnt) { sf[nt][0] = -1e30f; sf[nt][2] = -1e30f; }
            if (c + 1 >= cnt) { sf[nt][1] = -1e30f; sf[nt][3] = -1e30f; }
            bm0 = fmaxf(bm0, fmaxf(sf[nt][0], sf[nt][1]));
            bm1 = fmaxf(bm1, fmaxf(sf[nt][2], sf[nt][3]));
        }
        bm0 = fmaxf(bm0, __shfl_xor_sync(0xffffffffu, bm0, 1));
        bm0 = fmaxf(bm0, __shfl_xor_sync(0xffffffffu, bm0, 2));
        bm1 = fmaxf(bm1, __shfl_xor_sync(0xffffffffu, bm1, 1));
        bm1 = fmaxf(bm1, __shfl_xor_sync(0xffffffffu, bm1, 2));
        float nm0 = fmaxf(m0, bm0), nm1 = fmaxf(m1, bm1);
        float cor0 = ex2f(m0 - nm0), cor1 = ex2f(m1 - nm1);
        m0 = nm0; m1 = nm1;
        uint32_t pf01[8], pf23[8];
#pragma unroll
        for (int nt = 0; nt < 8; nt++) {
            pf01[nt] = h2ex2(f2h2(sf[nt][0] - nm0, sf[nt][1] - nm0));
            pf23[nt] = h2ex2(f2h2(sf[nt][2] - nm1, sf[nt][3] - nm1));
        }
#pragma unroll
        for (int nt = 0; nt < 4; nt++) {
            of[nt][0] *= cor0; of[nt][1] *= cor0;
            of[nt][2] *= cor1; of[nt][3] *= cor1;
        }
        float dn[4] = {0.f, 0.f, 0.f, 0.f};
#pragma unroll
        for (int ks = 0; ks < 4; ks++) {
            uint32_t a0 = pf01[2 * ks], a1 = pf23[2 * ks];
            uint32_t a2 = pf01[2 * ks + 1], a3 = pf23[2 * ks + 1];
#pragma unroll
            for (int nt = 0; nt < 4; nt++) {
                uint32_t b0 = VT[(nt * 8 + lq) * VSW2 + 8 * ks + lr];
                uint32_t b1 = VT[(nt * 8 + lq) * VSW2 + 8 * ks + lr + 4];
                mma16(of[nt], a0, a1, a2, a3, b0, b1);
            }
            mma16(dn, a0, a1, a2, a3, ones2, ones2);
        }
        den0 = den0 * cor0 + dn[0];
        den1 = den1 * cor1 + dn[2];
    }

    float i0 = 1.f / den0, i1 = 1.f / den1;
    int q_lo = qt * 128 + wid * 16 + lq, q_hi = q_lo + 8;
#pragma unroll
    for (int nt = 0; nt < 4; nt++) {
        int col = h * 32 + nt * 8 + lr * 2;
        if (q_lo < LMAX)
            *(uint32_t*)(g_attn16 + (size_t)(b * LMAX + q_lo) * DD + col) =
                f2h2(of[nt][0] * i0, of[nt][1] * i0);
        if (q_hi < LMAX)
            *(uint32_t*)(g_attn16 + (size_t)(b * LMAX + q_hi) * DD + col) =
                f2h2(of[nt][2] * i1, of[nt][3] * i1);
    }
}

// ---------------- GAT kernels (CSR, fp16 h3) ----------------
__global__ void zero_y_kernel() {
    size_t i = (size_t)blockIdx.x * blockDim.x + threadIdx.x;
    if (i < (size_t)NM * DD / 4) {
        ((float4*)g_y)[i] = make_float4(0.f, 0.f, 0.f, 0.f);
        ((uint2*)g_y16)[i] = make_uint2(0u, 0u);
    }
}

__global__ void gat_prep3(const float* __restrict__ a_src,
                          const float* __restrict__ a_dst)
{
    int gid = blockIdx.x * blockDim.x + threadIdx.x;
    int node = gid >> 5, lane = gid & 31;
    int hop = blockIdx.y;
    if (node >= NN) return;
    float s[4], d[4];
#pragma unroll
    for (int j = 0; j < 4; j++) {
        int c = j * 32 + lane;
        float hv = __half2float(g_h316[(size_t)node * 384 + hop * 128 + c]);
        s[j] = hv * a_src[hop * DD + c];
        d[j] = hv * a_dst[hop * DD + c];
    }
#pragma unroll
    for (int j = 0; j < 4; j++)
#pragma unroll
        for (int o = 16; o > 0; o >>= 1) {
            s[j] += __shfl_xor_sync(0xffffffffu, s[j], o);
            d[j] += __shfl_xor_sync(0xffffffffu, d[j], o);
        }
    if (lane == 0) {
        int idx = (node * 3 + hop) * 4;
        *(float4*)&g_als3[idx] = make_float4(s[0], s[1], s[2], s[3]);
        *(float4*)&g_ald3[idx] = make_float4(d[0], d[1], d[2], d[3]);
        g_deg[hop * NN + node] = 0;
    }
}

__global__ void deg3(const int* __restrict__ e0, const int* __restrict__ e1,
                     const int* __restrict__ e2)
{
    int hop = blockIdx.y;
    const int* ei = (hop == 0) ? e0 : (hop == 1) ? e1 : e2;
    int t = blockIdx.x * blockDim.x + threadIdx.x;
    if (t >= NITEMS) return;
    int dst = (t < NE) ? ei[NE + t] : t - NE;
    atomicAdd(&g_deg[hop * NN + dst], 1);
}

__global__ __launch_bounds__(1024) void scan3() {
    __shared__ int part[1024];
    const int hop = blockIdx.x;
    const int t = threadIdx.x;
    const int CH = (NN + 1023) / 1024;
    int beg = t * CH, end = beg + CH;
    if (end > NN) end = NN;
    int s = 0;
    for (int i = beg; i < end; i++) s += g_deg[hop * NN + i];
    part[t] = s;
    __syncthreads();
    for (int o = 1; o < 1024; o <<= 1) {
        int u = (t >= o) ? part[t - o] : 0;
        __syncthreads();
        part[t] += u;
        __syncthreads();
    }
    int run = part[t] - s;
    for (int i = beg; i < end; i++) {
        int d = g_deg[hop * NN + i];
        g_off[hop * (NN + 1) + i] = run;
        g_cur[hop * NN + i] = run;
        run += d;
    }
    if (t == 0) g_off[hop * (NN + 1) + NN] = NITEMS;
}

__global__ void edge_scat3(const int* __restrict__ e0, const int* __restrict__ e1,
                           const int* __restrict__ e2)
{
    int hop = blockIdx.y;
    const int* ei = (hop == 0) ? e0 : (hop == 1) ? e1 : e2;
    int t = blockIdx.x * blockDim.x + threadIdx.x;
    if (t >= NITEMS) return;
    int src, dst;
    if (t < NE) { src = ei[t]; dst = ei[NE + t]; }
    else { src = dst = t - NE; }
    float4 a = *(const float4*)&g_als3[(src * 3 + hop) * 4];
    float4 b = *(const float4*)&g_ald3[(dst * 3 + hop) * 4];
    float4 ew;
    ew.x = expf(leakyf(a.x + b.x, 0.2f));
    ew.y = expf(leakyf(a.y + b.y, 0.2f));
    ew.z = expf(leakyf(a.z + b.z, 0.2f));
    ew.w = expf(leakyf(a.w + b.w, 0.2f));
    int pos = atomicAdd(&g_cur[hop * NN + dst], 1);
    g_srcS[(size_t)hop * NITEMS + pos] = src;
    *(float4*)&g_ew[((size_t)hop * NITEMS + pos) * 4] = ew;
}

// aggregation: warp per (dst, hop); half2 loads + 2-stage pipelined edge loop
__global__ void aggr3(const float* __restrict__ bias) {
    int gid = blockIdx.x * blockDim.x + threadIdx.x;
    int dst = gid >> 5, lane = gid & 31;
    int hop = blockIdx.y;
    if (dst >= NN) return;
    int e0 = g_off[hop * (NN + 1) + dst];
    int e1 = g_off[hop * (NN + 1) + dst + 1];
    const float4* ewp = (const float4*)g_ew + (size_t)hop * NITEMS;
    const int* srcp = g_srcS + (size_t)hop * NITEMS;

    // denominators (4 heads)
    float4 den = make_float4(0.f, 0.f, 0.f, 0.f);
    for (int e = e0 + lane; e < e1; e += 32) {
        float4 w4 = ewp[e];
        den.x += w4.x; den.y += w4.y; den.z += w4.z; den.w += w4.w;
    }
#pragma unroll
    for (int o = 16; o > 0; o >>= 1) {
        den.x += __shfl_xor_sync(0xffffffffu, den.x, o);
        den.y += __shfl_xor_sync(0xffffffffu, den.y, o);
        den.z += __shfl_xor_sync(0xffffffffu, den.z, o);
        den.w += __shfl_xor_sync(0xffffffffu, den.w, o);
    }
    const bool lo = (lane < 16);
    const float inv0 = 1.f / (lo ? den.x : den.y);   // lane handles cols 2l..2l+1 (heads 0/1)
    const float inv1 = 1.f / (lo ? den.z : den.w);   // and cols 64+2l..65+2l (heads 2/3)

    float2 a0 = make_float2(0.f, 0.f), a1 = make_float2(0.f, 0.f);
    // 2-stage software pipeline over the bucket
    float4 w_n = make_float4(0.f, 0.f, 0.f, 0.f);
    __half2 h0_n, h1_n;
    if (e0 < e1) {
        w_n = ewp[e0];
        const __half2* hp = (const __half2*)(g_h316 + (size_t)srcp[e0] * 384 + hop * 128);
        h0_n = hp[lane]; h1_n = hp[32 + lane];
    }
    for (int e = e0; e < e1; e++) {
        float4 w = w_n;
        __half2 h0 = h0_n, h1 = h1_n;
        if (e + 1 < e1) {
            w_n = ewp[e + 1];
            const __half2* hp = (const __half2*)(g_h316 + (size_t)srcp[e + 1] * 384 + hop * 128);
            h0_n = hp[lane]; h1_n = hp[32 + lane];
        }
        float al0 = (lo ? w.x : w.y) * inv0;
        float al1 = (lo ? w.z : w.w) * inv1;
        float2 f0 = __half22float2(h0), f1 = __half22float2(h1);
        a0.x += al0 * f0.x; a0.y += al0 * f0.y;
        a1.x += al1 * f1.x; a1.y += al1 * f1.y;
    }

    __half2* gd = (__half2*)(g_gout316 + (size_t)dst * 384 + hop * 128);
    const float* bb = bias + hop * 128;
    gd[lane]      = __floats2half2_rn(a0.x + bb[2 * lane], a0.y + bb[2 * lane + 1]);
    gd[32 + lane] = __floats2half2_rn(a1.x + bb[64 + 2 * lane], a1.y + bb[64 + 2 * lane + 1]);
}

// ---------------- fused sequence-position kernel ----------------
__global__ __launch_bounds__(256) void seq_kernel(const int* __restrict__ genre) {
    __shared__ int ch[NCHUNK * NG];
    int tid = threadIdx.x;
    if (tid < NCHUNK) {
        for (int g = 0; g < NG; g++) ch[tid * NG + g] = 0;
        int base = tid * 128;
        int end = base + 128; if (end > NM) end = NM;
        for (int i = base; i < end; i++) ch[tid * NG + genre[i]]++;
    }
    __syncthreads();
    if (tid < NG) {
        int run = 0;
        for (int c = 0; c < NCHUNK; c++) {
            int t = ch[c * NG + tid];
            ch[c * NG + tid] = run;
            run += t;
        }
        g_cnt[tid] = run;
    }
    __syncthreads();
    if (tid < NCHUNK) {
        int base = tid * 128;
        int end = base + 128; if (end > NM) end = NM;
        for (int i = base; i < end; i++) {
            int g = genre[i];
            g_pos[i] = ch[tid * NG + g]++;
        }
    }
}

__global__ void gather_kernel(const int* __restrict__ movie_idx, const int* __restrict__ genre,
                              const float* __restrict__ src)
{
    int t = blockIdx.x * blockDim.x + threadIdx.x;
    if (t >= NM * 32) return;
    int i = t >> 5, c4 = (t & 31) * 4;
    float4 v = *(const float4*)&src[(size_t)movie_idx[i] * DD + c4];
    uint2 h2 = make_uint2(f2h2(v.x, v.y), f2h2(v.z, v.w));
    *(uint2*)(g_xm16 + (size_t)i * DD + c4) = h2;
    int row = genre[i] * LMAX + g_pos[i];
    *(float4*)&g_y[(size_t)row * DD + c4] = v;
    *(uint2*)(g_y16 + (size_t)row * DD + c4) = h2;
}

// ---------------- fused pool + pe ----------------
__global__ void pool_pe(const float* __restrict__ fus_w) {
    __shared__ float pr[DD];
    int g = blockIdx.x, d = threadIdx.x;
    int cnt = g_cnt[g];
    float s = 0.f;
    for (int t = 0; t < cnt; t++) s += g_y[(size_t)(g * LMAX + t) * DD + d];
    pr[d] = s / fmaxf((float)cnt, 1.f);
    __syncthreads();
    float acc = 0.f;
    for (int k = 0; k < DD; k++)
        acc += pr[k] * fus_w[d * 256 + 128 + k];
    g_pe[g * DD + d] = acc;
}

// ---------------- launch ----------------
extern "C" void kernel_launch(void* const* d_in, const int* in_sizes, int n_in,
                              void* d_out, int out_size)
{
    const float* x        = (const float*)d_in[0];
    const int*   e0       = (const int*)d_in[1];
    const int*   e1       = (const int*)d_in[2];
    const int*   e2       = (const int*)d_in[3];
    const int*   movie_idx = (const int*)d_in[4];
    const int*   genre     = (const int*)d_in[5];
    const float* gat_W    = (const float*)d_in[6];
    const float* att_src  = (const float*)d_in[7];
    const float* att_dst  = (const float*)d_in[8];
    const float* gat_bias = (const float*)d_in[9];
    const float* dec_W    = (const float*)d_in[10];
    const float* dec_b    = (const float*)d_in[11];
    const float* qkv_w    = (const float*)d_in[12];
    const float* qkv_b    = (const float*)d_in[13];
    const float* out_w    = (const float*)d_in[14];
    const float* out_b    = (const float*)d_in[15];
    const float* ln1_g    = (const float*)d_in[16];
    const float* ln1_b    = (const float*)d_in[17];
    const float* ln2_g    = (const float*)d_in[18];
    const float* ln2_b    = (const float*)d_in[19];
    const float* ffn_w1   = (const float*)d_in[20];
    const float* ffn_b1   = (const float*)d_in[21];
    const float* ffn_w2   = (const float*)d_in[22];
    const float* ffn_b2   = (const float*)d_in[23];
    const float* fus_w    = (const float*)d_in[24];
    const float* fus_b    = (const float*)d_in[25];
    float* out = (float*)d_out;

    float *p_y;
    __half *p_x16, *p_h316, *p_gout316, *p_y16, *p_qkv16, *p_attn16, *p_ffn16, *p_xm16;
    __half *p_gatW16, *p_decW16, *p_qkvW16, *p_outW16, *p_fw116, *p_fw216, *p_fusW16;
    cudaGetSymbolAddress((void**)&p_y,      g_y);
    cudaGetSymbolAddress((void**)&p_x16,    g_x16);
    cudaGetSymbolAddress((void**)&p_h316,   g_h316);
    cudaGetSymbolAddress((void**)&p_gout316, g_gout316);
    cudaGetSymbolAddress((void**)&p_y16,    g_y16);
    cudaGetSymbolAddress((void**)&p_qkv16,  g_qkv16);
    cudaGetSymbolAddress((void**)&p_attn16, g_attn16);
    cudaGetSymbolAddress((void**)&p_ffn16,  g_ffn16);
    cudaGetSymbolAddress((void**)&p_xm16,   g_xm16);
    cudaGetSymbolAddress((void**)&p_gatW16, g_gatW16);
    cudaGetSymbolAddress((void**)&p_decW16, g_decW16);
    cudaGetSymbolAddress((void**)&p_qkvW16, g_qkvW16);
    cudaGetSymbolAddress((void**)&p_outW16, g_outW16);
    cudaGetSymbolAddress((void**)&p_fw116,  g_fw116);
    cudaGetSymbolAddress((void**)&p_fw216,  g_fw216);
    cudaGetSymbolAddress((void**)&p_fusW16, g_fusW16);

    const int GSMEM = 4 * TBUF * 4;          // 40960 B
    const int LNSMEM = 128 * LNS * 4;        // 67584 B
    cudaFuncSetAttribute(gemm_mma, cudaFuncAttributeMaxDynamicSharedMemorySize, GSMEM);
    cudaFuncSetAttribute(gemm_dec, cudaFuncAttributeMaxDynamicSharedMemorySize, GSMEM);
    cudaFuncSetAttribute(gemm_fuse, cudaFuncAttributeMaxDynamicSharedMemorySize, GSMEM);
    cudaFuncSetAttribute(gemm_ln, cudaFuncAttributeMaxDynamicSharedMemorySize, LNSMEM);

    const int MTN = (NN + 127) / 128;  // 391
    const int MT  = (NM + 127) / 128;  // 160

    // -------- one-shot fp16 conversions (single launch) --------
    F2HBatch fb2;
    fb2.src[0] = x;      fb2.dst[0] = p_x16;    fb2.n4[0] = NN * DD / 4;
    fb2.src[1] = gat_W;  fb2.dst[1] = p_gatW16; fb2.n4[1] = 3 * DD * DD / 4;
    fb2.src[2] = dec_W;  fb2.dst[2] = p_decW16; fb2.n4[2] = 3 * DD * DD / 4;
    fb2.src[3] = qkv_w;  fb2.dst[3] = p_qkvW16; fb2.n4[3] = NL * 3 * DD * DD / 4;
    fb2.src[4] = out_w;  fb2.dst[4] = p_outW16; fb2.n4[4] = NL * DD * DD / 4;
    fb2.src[5] = ffn_w1; fb2.dst[5] = p_fw116;  fb2.n4[5] = NL * FFD * DD / 4;
    fb2.src[6] = ffn_w2; fb2.dst[6] = p_fw216;  fb2.n4[6] = NL * DD * FFD / 4;
    fb2.src[7] = fus_w;  fb2.dst[7] = p_fusW16; fb2.n4[7] = DD * 256 / 4;
    f2h_multi<<<dim3(592, 8), 256>>>(fb2);

    // -------- GAT --------
    gemm_mma<<<dim3(3, MTN), 256, GSMEM>>>(p_x16, p_gatW16, nullptr, nullptr, p_h316,
                                           NN, 384, DD, DD, DD, 3);
    gat_prep3<<<dim3((NN * 32 + 255) / 256, 3), 256>>>(att_src, att_dst);
    deg3<<<dim3((NITEMS + 255) / 256, 3), 256>>>(e0, e1, e2);
    scan3<<<3, 1024>>>();
    edge_scat3<<<dim3((NITEMS + 255) / 256, 3), 256>>>(e0, e1, e2);
    aggr3<<<dim3((NN * 32 + 255) / 256, 3), 256>>>(gat_bias);
    gemm_dec<<<dim3(1, MTN), 256, GSMEM>>>(p_gout316, p_decW16, dec_b, out, NN);

    // -------- build genre sequences --------
    seq_kernel<<<1, 256>>>(genre);
    zero_y_kernel<<<(NM * DD / 4 + 255) / 256, 256>>>();
    gather_kernel<<<(NM * 32 + 255) / 256, 256>>>(movie_idx, genre, out);

    // -------- transformer (4 layers) --------
    for (int l = 0; l < NL; l++) {
        gemm_mma<<<dim3(3 * DD / 128, MT), 256, GSMEM>>>(
            p_y16, p_qkvW16 + (size_t)l * 3 * DD * DD, qkv_b + l * 3 * DD,
            nullptr, p_qkv16, NM, 3 * DD, DD, DD, DD, 3);
        attn_tc<<<dim3((LMAX + 127) / 128, NHEADS, NG), 256>>>();
        gemm_ln<<<dim3(1, MT), 256, LNSMEM>>>(
            p_attn16, p_outW16 + (size_t)l * DD * DD, out_b + l * DD,
            ln1_g + l * DD, ln1_b + l * DD, p_y, p_y16, NM, DD);
        gemm_mma<<<dim3(FFD / 128, MT), 256, GSMEM>>>(
            p_y16, p_fw116 + (size_t)l * FFD * DD, ffn_b1 + l * FFD,
            nullptr, p_ffn16, NM, FFD, DD, DD, DD, 4);
        gemm_ln<<<dim3(1, MT), 256, LNSMEM>>>(
            p_ffn16, p_fw216 + (size_t)l * DD * FFD, ffn_b2 + l * DD,
            ln2_g + l * DD, ln2_b + l * DD, p_y, p_y16, NM, FFD);
    }

    // -------- pool + fused final GEMM --------
    pool_pe<<<NG, DD>>>(fus_w);
    gemm_fuse<<<dim3(1, MT), 256, GSMEM>>>(p_xm16, p_fusW16, movie_idx, genre,
                                           fus_b, out, NM);
}